// round 1
// baseline (speedup 1.0000x reference)
#include <cuda_runtime.h>
#include <cuda_bf16.h>
#include <math.h>

#define BB 8
#define NN 1025
#define CC 1024
#define HH 16
#define DD 64
#define MM 25
#define KK 25
#define TOT (BB*NN)           // 8200
#define QKVLD 3072
#define SCALE 0.125f          // 64^-0.5

// ---------------- scratch (static device globals; no allocation) ----------------
__device__ float g_qkv[TOT * QKVLD];          // [b,n, q|k|v interleaved by 1024]
__device__ float g_router[BB * MM * CC];      // [b,m,c]
__device__ float g_rlog[BB * HH * MM * NN];   // [bh, m, n]
__device__ float g_gate[BB * HH * MM * NN];   // [bh, m, n]
__device__ float g_av[BB * HH * MM * DD];     // [bh, m, d]
__device__ int   g_topk[BB * HH * MM * KK];   // [bh, m, k]
__device__ int   g_expert[BB * HH * NN];      // [bh, n]
__device__ float g_attn[TOT * CC];            // [b,n, h*64+d]

// ---------------- SGEMM: 128x128 tile, BK=8, 256 threads, 8x8/thread ----------------
template<bool BIAS>
__global__ void sgemm_kernel(const float* __restrict__ A, const float* __restrict__ B,
                             const float* __restrict__ bias, float* __restrict__ C,
                             int M, int N, int K) {
    __shared__ float As[8][128];
    __shared__ float Bs[8][128];
    const int tid = threadIdx.x;
    const int tx = tid & 15, ty = tid >> 4;
    const int brow = blockIdx.y * 128, bcol = blockIdx.x * 128;

    const int arow = tid >> 1;
    const int acol = (tid & 1) * 4;
    const int bkrow = tid >> 5;
    const int bncol = (tid & 31) * 4;

    const bool arow_ok = (brow + arow) < M;
    const float* Aptr = A + (size_t)(brow + arow) * K + acol;
    const float* Bptr = B + (size_t)bkrow * N + bcol + bncol;

    float acc[8][8];
    #pragma unroll
    for (int i = 0; i < 8; i++)
        #pragma unroll
        for (int j = 0; j < 8; j++) acc[i][j] = 0.0f;

    for (int kt = 0; kt < K; kt += 8) {
        float4 av = arow_ok ? *(const float4*)(Aptr + kt) : make_float4(0.f,0.f,0.f,0.f);
        float4 bv = *(const float4*)(Bptr + (size_t)kt * N);
        __syncthreads();
        As[acol+0][arow] = av.x; As[acol+1][arow] = av.y;
        As[acol+2][arow] = av.z; As[acol+3][arow] = av.w;
        *(float4*)&Bs[bkrow][bncol] = bv;
        __syncthreads();
        #pragma unroll
        for (int k = 0; k < 8; k++) {
            float4 a0 = ((const float4*)As[k])[ty];
            float4 a1 = ((const float4*)As[k])[16 + ty];
            float4 b0 = ((const float4*)Bs[k])[tx];
            float4 b1 = ((const float4*)Bs[k])[16 + tx];
            float a[8] = {a0.x,a0.y,a0.z,a0.w,a1.x,a1.y,a1.z,a1.w};
            float b[8] = {b0.x,b0.y,b0.z,b0.w,b1.x,b1.y,b1.z,b1.w};
            #pragma unroll
            for (int i = 0; i < 8; i++)
                #pragma unroll
                for (int j = 0; j < 8; j++)
                    acc[i][j] += a[i] * b[j];
        }
    }

    #pragma unroll
    for (int i = 0; i < 8; i++) {
        int r = brow + (i < 4 ? ty*4 + i : 64 + ty*4 + (i-4));
        if (r >= M) continue;
        int c0 = bcol + tx*4;
        int c1 = bcol + 64 + tx*4;
        float4 o0, o1;
        o0.x = acc[i][0]; o0.y = acc[i][1]; o0.z = acc[i][2]; o0.w = acc[i][3];
        o1.x = acc[i][4]; o1.y = acc[i][5]; o1.z = acc[i][6]; o1.w = acc[i][7];
        if (BIAS) {
            o0.x += bias[c0+0]; o0.y += bias[c0+1]; o0.z += bias[c0+2]; o0.w += bias[c0+3];
            o1.x += bias[c1+0]; o1.y += bias[c1+1]; o1.z += bias[c1+2]; o1.w += bias[c1+3];
        }
        *(float4*)&C[(size_t)r * N + c0] = o0;
        *(float4*)&C[(size_t)r * N + c1] = o1;
    }
}

// ---------------- Router: adaptive avg pool of q (32x32 -> 5x5) ----------------
__global__ void router_kernel(const float* __restrict__ qkv, float* __restrict__ router) {
    const int m = blockIdx.x;       // 0..24
    const int b = blockIdx.y;       // 0..7
    const int i = m / 5, j = m % 5;
    const int s[5] = {0, 6, 12, 19, 25};
    const int e[5] = {7, 13, 20, 26, 32};
    const float inv = 1.0f / (float)((e[i]-s[i]) * (e[j]-s[j]));
    for (int c = threadIdx.x; c < CC; c += blockDim.x) {
        float acc = 0.0f;
        for (int gh = s[i]; gh < e[i]; gh++)
            for (int gw = s[j]; gw < e[j]; gw++)
                acc += qkv[(size_t)(b*NN + gh*32 + gw) * QKVLD + c];
        router[(size_t)(b*MM + m) * CC + c] = acc * inv;
    }
}

// ---------------- r_logits = r@k^T, gate = r@q^T, per (b,h) ----------------
__global__ void rg_kernel(const float* __restrict__ qkv, const float* __restrict__ router,
                          float* __restrict__ rlog, float* __restrict__ gate) {
    const int bh = blockIdx.y;
    const int b = bh >> 4, h = bh & 15;
    const int t0 = blockIdx.x * 256;
    const int tid = threadIdx.x;
    __shared__ float rsm[25][64];
    __shared__ float ks[256][17];
    __shared__ float qs[256][17];

    for (int idx = tid; idx < 1600; idx += 256)
        rsm[idx >> 6][idx & 63] = router[(size_t)(b*MM + (idx >> 6)) * CC + h*64 + (idx & 63)];

    float acc_k[25], acc_q[25];
    #pragma unroll
    for (int m = 0; m < 25; m++) { acc_k[m] = 0.0f; acc_q[m] = 0.0f; }

    const int n = t0 + tid;
    for (int dc = 0; dc < 64; dc += 16) {
        __syncthreads();
        for (int idx = tid; idx < 256*16; idx += 256) {
            int tok = idx >> 4, dd = idx & 15;
            int gn = t0 + tok;
            float kv = 0.0f, qv = 0.0f;
            if (gn < NN) {
                const float* base = qkv + (size_t)(b*NN + gn) * QKVLD + h*64 + dc + dd;
                qv = base[0];
                kv = base[1024];
            }
            ks[tok][dd] = kv; qs[tok][dd] = qv;
        }
        __syncthreads();
        #pragma unroll
        for (int d = 0; d < 16; d++) {
            float kd = ks[tid][d], qd = qs[tid][d];
            #pragma unroll
            for (int m = 0; m < 25; m++) {
                float r = rsm[m][dc + d];
                acc_k[m] += r * kd;
                acc_q[m] += r * qd;
            }
        }
    }
    if (n < NN) {
        #pragma unroll
        for (int m = 0; m < 25; m++) {
            rlog[((size_t)bh*MM + m) * NN + n] = acc_k[m];
            gate[((size_t)bh*MM + m) * NN + n] = acc_q[m];
        }
    }
}

// ---------------- Agent branch: softmax(r_logits*scale) @ V ----------------
__global__ void agent_kernel(const float* __restrict__ rlog, const float* __restrict__ qkv,
                             float* __restrict__ av) {
    const int bhm = blockIdx.x;           // bh*25 + m
    const int bh = bhm / 25;
    const int b = bh >> 4, h = bh & 15;
    const float* row = rlog + (size_t)bhm * NN;
    __shared__ float p[NN];
    __shared__ float red[128];
    const int tid = threadIdx.x;          // 128

    float mx = -INFINITY;
    for (int n = tid; n < NN; n += 128) mx = fmaxf(mx, row[n]);
    red[tid] = mx; __syncthreads();
    for (int s = 64; s > 0; s >>= 1) {
        if (tid < s) red[tid] = fmaxf(red[tid], red[tid + s]);
        __syncthreads();
    }
    mx = red[0];
    __syncthreads();

    float sum = 0.0f;
    for (int n = tid; n < NN; n += 128) {
        float e = __expf((row[n] - mx) * SCALE);
        p[n] = e; sum += e;
    }
    red[tid] = sum; __syncthreads();
    for (int s = 64; s > 0; s >>= 1) {
        if (tid < s) red[tid] += red[tid + s];
        __syncthreads();
    }
    const float inv = 1.0f / red[0];

    if (tid < 64) {
        const int d = tid;
        const float* vbase = qkv + (size_t)b*NN*QKVLD + 2048 + h*64 + d;
        float acc = 0.0f;
        for (int n = 0; n < NN; n++) acc += p[n] * vbase[(size_t)n * QKVLD];
        av[(size_t)bhm * 64 + d] = acc * inv;
    }
}

// ---------------- Top-25 key indices per (bh,m) ----------------
__global__ void topk_kernel(const float* __restrict__ rlog, int* __restrict__ topk) {
    const int bhm = blockIdx.x;
    __shared__ float vals[NN];
    __shared__ float bmax[256];
    __shared__ int bidx[256];
    const int tid = threadIdx.x;          // 256
    for (int n = tid; n < NN; n += 256) vals[n] = rlog[(size_t)bhm * NN + n];
    __syncthreads();
    for (int it = 0; it < 25; it++) {
        float best = -INFINITY; int bi = NN;
        for (int n = tid; n < NN; n += 256) {
            float v = vals[n];
            if (v > best || (v == best && n < bi)) { best = v; bi = n; }
        }
        bmax[tid] = best; bidx[tid] = bi; __syncthreads();
        for (int s = 128; s > 0; s >>= 1) {
            if (tid < s) {
                if (bmax[tid+s] > bmax[tid] ||
                    (bmax[tid+s] == bmax[tid] && bidx[tid+s] < bidx[tid])) {
                    bmax[tid] = bmax[tid+s]; bidx[tid] = bidx[tid+s];
                }
            }
            __syncthreads();
        }
        if (tid == 0) {
            topk[bhm * 25 + it] = bidx[0];
            vals[bidx[0]] = -INFINITY;
        }
        __syncthreads();
    }
}

// ---------------- Per-query expert argmax ----------------
__global__ void expert_kernel(const float* __restrict__ gate, int* __restrict__ expert) {
    const int idx = blockIdx.x * 256 + threadIdx.x;   // bh*NN + n
    if (idx >= BB*HH*NN) return;
    const int bh = idx / NN, n = idx % NN;
    const float* g = gate + (size_t)bh * MM * NN + n;
    float best = g[0]; int bi = 0;
    #pragma unroll
    for (int m = 1; m < 25; m++) {
        float v = g[(size_t)m * NN];
        if (v > best) { best = v; bi = m; }
    }
    expert[idx] = bi;
}

// ---------------- Mixed attention: merged softmax over [25 agents | 25 selected keys] ----------------
__global__ void mixed_kernel(const float* __restrict__ qkv, const float* __restrict__ gate,
                             const float* __restrict__ av, const int* __restrict__ topk,
                             const int* __restrict__ expert, float* __restrict__ attn) {
    const int bh = blockIdx.y;
    const int b = bh >> 4, h = bh & 15;
    const int tid = threadIdx.x, lane = tid & 31, w = tid >> 5;
    __shared__ float avs[25][64];
    __shared__ float ws[8][50];
    for (int idx = tid; idx < 1600; idx += 256)
        avs[idx >> 6][idx & 63] = av[(size_t)bh * 1600 + idx];
    __syncthreads();

    const int n = blockIdx.x * 8 + w;
    if (n >= NN) return;

    const int e = expert[bh * NN + n];
    const int sel = (lane < 25) ? topk[((size_t)bh*MM + e) * 25 + lane] : 0;

    const float* qrow = qkv + (size_t)(b*NN + n) * QKVLD + h*64;
    const float qa = qrow[lane], qb = qrow[lane + 32];
    const float* kb = qkv + (size_t)b*NN*QKVLD + 1024 + h*64;
    const float* vb = qkv + (size_t)b*NN*QKVLD + 2048 + h*64;

    float L0 = -INFINITY, L1 = -INFINITY;
    if (lane < 25) L0 = gate[((size_t)bh*MM + lane) * NN + n] * SCALE;

    #pragma unroll
    for (int k = 0; k < 25; k++) {
        int s = __shfl_sync(0xffffffffu, sel, k);
        const float* kr = kb + (size_t)s * QKVLD;
        float part = qa * kr[lane] + qb * kr[lane + 32];
        #pragma unroll
        for (int o = 16; o > 0; o >>= 1) part += __shfl_xor_sync(0xffffffffu, part, o);
        part *= SCALE;
        const int j = 25 + k;
        if (j < 32) { if (lane == j) L0 = part; }
        else        { if (lane == j - 32) L1 = part; }
    }

    float mx = fmaxf(L0, L1);
    #pragma unroll
    for (int o = 16; o > 0; o >>= 1) mx = fmaxf(mx, __shfl_xor_sync(0xffffffffu, mx, o));
    float p0 = __expf(L0 - mx), p1 = __expf(L1 - mx);
    float ssum = p0 + p1;
    #pragma unroll
    for (int o = 16; o > 0; o >>= 1) ssum += __shfl_xor_sync(0xffffffffu, ssum, o);
    const float invs = 1.0f / ssum;

    ws[w][lane] = p0 * invs;
    if (lane < 18) ws[w][32 + lane] = p1 * invs;
    __syncwarp();

    float o0 = 0.0f, o1 = 0.0f;
    #pragma unroll
    for (int m = 0; m < 25; m++) {
        float wt = ws[w][m];
        o0 += wt * avs[m][lane];
        o1 += wt * avs[m][lane + 32];
    }
    #pragma unroll
    for (int k = 0; k < 25; k++) {
        float wt = ws[w][25 + k];
        int s = __shfl_sync(0xffffffffu, sel, k);
        const float* vr = vb + (size_t)s * QKVLD;
        o0 += wt * vr[lane];
        o1 += wt * vr[lane + 32];
    }
    attn[(size_t)(b*NN + n) * CC + h*64 + lane] = o0;
    attn[(size_t)(b*NN + n) * CC + h*64 + lane + 32] = o1;
}

// ---------------- launch ----------------
extern "C" void kernel_launch(void* const* d_in, const int* in_sizes, int n_in,
                              void* d_out, int out_size) {
    const float* x     = (const float*)d_in[0];   // [8,1025,1024]
    const float* Wqkv  = (const float*)d_in[1];   // [1024,3072]
    const float* Wproj = (const float*)d_in[2];   // [1024,1024]
    const float* bproj = (const float*)d_in[3];   // [1024]
    float* out = (float*)d_out;                   // [8,1025,1024]

    float *qkv_p, *router_p, *rlog_p, *gate_p, *av_p, *attn_p;
    int *topk_p, *expert_p;
    cudaGetSymbolAddress((void**)&qkv_p,    g_qkv);
    cudaGetSymbolAddress((void**)&router_p, g_router);
    cudaGetSymbolAddress((void**)&rlog_p,   g_rlog);
    cudaGetSymbolAddress((void**)&gate_p,   g_gate);
    cudaGetSymbolAddress((void**)&av_p,     g_av);
    cudaGetSymbolAddress((void**)&topk_p,   g_topk);
    cudaGetSymbolAddress((void**)&expert_p, g_expert);
    cudaGetSymbolAddress((void**)&attn_p,   g_attn);

    // 1) qkv = x @ Wqkv
    sgemm_kernel<false><<<dim3(QKVLD/128, (TOT+127)/128), 256>>>(
        x, Wqkv, nullptr, qkv_p, TOT, QKVLD, CC);

    // 2) router tokens via adaptive avg pool of q
    router_kernel<<<dim3(MM, BB), 256>>>(qkv_p, router_p);

    // 3) r_logits and gate
    rg_kernel<<<dim3((NN+255)/256, BB*HH), 256>>>(qkv_p, router_p, rlog_p, gate_p);

    // 4) agent values
    agent_kernel<<<BB*HH*MM, 128>>>(rlog_p, qkv_p, av_p);

    // 5) top-25 keys per expert
    topk_kernel<<<BB*HH*MM, 256>>>(rlog_p, topk_p);

    // 6) per-query expert
    expert_kernel<<<(BB*HH*NN + 255)/256, 256>>>(gate_p, expert_p);

    // 7) mixed attention
    mixed_kernel<<<dim3((NN+7)/8, BB*HH), 256>>>(qkv_p, gate_p, av_p, topk_p, expert_p, attn_p);

    // 8) out = attn @ Wproj + bproj
    sgemm_kernel<true><<<dim3(CC/128, (TOT+127)/128), 256>>>(
        attn_p, Wproj, bproj, out, TOT, CC, CC);
}